// round 2
// baseline (speedup 1.0000x reference)
#include <cuda_runtime.h>
#include <cstdint>
#include <math.h>

#define BB 16
#define TT 4096
#define JJ 17
#define CC 128
#define HH 512
#define KK 2048
#define BT (BB*TT)

#define SEL_ELEMS (BB*KK*JJ*CC)   // 71303168
#define IDX_ELEMS (BB*KK)         // 32768

// ---- scratch (static device arrays; no allocation allowed) ----
__device__ float g_stn[BT*CC];          // layernormed joint-mean  [B*T, C]
__device__ float g_gc_part[BB*32*CC];   // partial sums for global context
__device__ float g_gc[BB*CC];           // global context  [B, C]
__device__ float g_scores[BT];          // raw MLP scores  [B*T]
__device__ int   g_selidx[BB*KK];       // selected indices, ascending per batch
__device__ float g_gate[BB*KK];         // 1 + 0.1*sigmoid(score)

// ---------------- f32x2 helpers (Blackwell packed fp32) ----------------
__device__ __forceinline__ unsigned long long pack2(float x) {
    unsigned long long r;
    asm("mov.b64 %0, {%1, %1};" : "=l"(r) : "f"(x));
    return r;
}
__device__ __forceinline__ unsigned long long fma2(unsigned long long a,
                                                   unsigned long long b,
                                                   unsigned long long c) {
    unsigned long long d;
    asm("fma.rn.f32x2 %0, %1, %2, %3;" : "=l"(d) : "l"(a), "l"(b), "l"(c));
    return d;
}
__device__ __forceinline__ float2 unpack2(unsigned long long v) {
    float lo, hi;
    asm("mov.b64 {%0, %1}, %2;" : "=f"(lo), "=f"(hi) : "l"(v));
    return make_float2(lo, hi);
}

__device__ __forceinline__ float gelu_exact(float x) {
    return 0.5f * x * (1.0f + erff(x * 0.70710678118654752440f));
}

// ---------------- Kernel 1: joint mean + LayerNorm ----------------
__global__ void __launch_bounds__(128) mean_ln_kernel(
    const float* __restrict__ tokens,
    const float* __restrict__ ln_w,
    const float* __restrict__ ln_b)
{
    int bt = blockIdx.x;
    int c  = threadIdx.x;
    const float* src = tokens + (size_t)bt * (JJ*CC) + c;
    float s = 0.f;
#pragma unroll
    for (int j = 0; j < JJ; ++j) s += src[(size_t)j*CC];
    float st = s * (1.0f/17.0f);

    __shared__ float red[64];
    float v = st, v2 = st*st;
#pragma unroll
    for (int o = 16; o; o >>= 1) {
        v  += __shfl_down_sync(0xffffffffu, v,  o);
        v2 += __shfl_down_sync(0xffffffffu, v2, o);
    }
    int wid = c >> 5, lane = c & 31;
    if (lane == 0) { red[wid] = v; red[32+wid] = v2; }
    __syncthreads();
    if (c == 0) {
        float a = red[0]+red[1]+red[2]+red[3];
        float b = red[32]+red[33]+red[34]+red[35];
        red[40] = a * (1.0f/128.0f);
        red[41] = b * (1.0f/128.0f);
    }
    __syncthreads();
    float mu  = red[40];
    float var = red[41] - mu*mu;
    float inv = rsqrtf(var + 1e-5f);
    g_stn[(size_t)bt*CC + c] = (st - mu) * inv * ln_w[c] + ln_b[c];
}

// ---------------- Kernel 2/3: global context reduce ----------------
__global__ void __launch_bounds__(128) gc_partial_kernel()
{
    int b = blockIdx.x, chunk = blockIdx.y, c = threadIdx.x;
    const float* p = g_stn + ((size_t)(b*TT + chunk*128))*CC + c;
    float s = 0.f;
#pragma unroll 8
    for (int t = 0; t < 128; ++t) s += p[(size_t)t*CC];
    g_gc_part[(b*32 + chunk)*CC + c] = s;
}

__global__ void __launch_bounds__(128) gc_final_kernel()
{
    int b = blockIdx.x, c = threadIdx.x;
    float s = 0.f;
#pragma unroll
    for (int k = 0; k < 32; ++k) s += g_gc_part[(b*32 + k)*CC + c];
    g_gc[b*CC + c] = s * (1.0f/4096.0f);
}

// ---------------- Kernel 4: MLP scoring (fp32 GEMM via f32x2) ----------------
// 512 threads, tile 128 tokens x 128 h per chunk (4 chunks of H=512).
// Thread tile: 4 tokens x 8 h.  x in natural [t][k] layout (pitch 132),
// w pairs packed free from ws rows.
#define XPITCH 132
#define PPITCH 132
#define MLP_SMEM ((128*XPITCH + 128*128 + 16*PPITCH) * 4)
__global__ void __launch_bounds__(512) mlp_kernel(
    const float* __restrict__ W1,
    const float* __restrict__ b1,
    const float* __restrict__ W2,
    const float* __restrict__ b2)
{
    extern __shared__ float sh[];
    float* xs   = sh;                       // [t=128][k pitch 132]
    float* ws   = sh + 128*XPITCH;          // [k=128][h=128]
    float* part = sh + 128*XPITCH + 128*128; // [16][pitch 132]

    int tid = threadIdx.x;
    int g0  = blockIdx.x * 128;
    int b   = g0 >> 12;

    // load x tile (natural layout) with gc added; fully coalesced, conflict-free
#pragma unroll
    for (int r = 0; r < 8; ++r) {
        int i  = r*512 + tid;        // covers 128 t x 32 k-quads
        int t  = i >> 5;
        int kq = (i & 31) * 4;
        float4 x4 = *(const float4*)(g_stn + (size_t)(g0 + t)*CC + kq);
        float4 g4 = *(const float4*)(g_gc + b*CC + kq);
        x4.x += g4.x; x4.y += g4.y; x4.z += g4.z; x4.w += g4.w;
        *(float4*)(xs + t*XPITCH + kq) = x4;
    }

    int tx = tid & 15;            // h-group: h0 = tx*8  (covers 128 h)
    int ty = tid >> 4;            // t-group: t0 = ty*4  (covers 128 t)
    int h0 = tx * 8;
    int t0 = ty * 4;

    float sp[4] = {0.f, 0.f, 0.f, 0.f};

    for (int hc = 0; hc < 4; ++hc) {
        __syncthreads();   // xs ready (first iter) / previous ws consumed
#pragma unroll
        for (int r = 0; r < 8; ++r) {
            int i = r*512 + tid;
            int k = i >> 5;
            int q = (i & 31) * 4;
            *(float4*)(ws + k*128 + q) =
                *(const float4*)(W1 + (size_t)k*HH + hc*128 + q);
        }
        __syncthreads();

        unsigned long long acc[4][4];
#pragma unroll
        for (int i = 0; i < 4; ++i)
#pragma unroll
            for (int j = 0; j < 4; ++j) acc[i][j] = 0ull;

#pragma unroll 4
        for (int k = 0; k < 128; k += 2) {
            // w pairs for h0..h7, two consecutive k's (packed free)
            ulonglong2 wA0 = *(const ulonglong2*)(ws + k*128 + h0);
            ulonglong2 wB0 = *(const ulonglong2*)(ws + k*128 + h0 + 4);
            ulonglong2 wA1 = *(const ulonglong2*)(ws + (k+1)*128 + h0);
            ulonglong2 wB1 = *(const ulonglong2*)(ws + (k+1)*128 + h0 + 4);
#pragma unroll
            for (int i = 0; i < 4; ++i) {
                unsigned long long xk =
                    *(const unsigned long long*)(xs + (t0+i)*XPITCH + k);
                float2 xf = unpack2(xk);
                unsigned long long xl = pack2(xf.x);
                unsigned long long xh = pack2(xf.y);
                acc[i][0] = fma2(xl, wA0.x, acc[i][0]);
                acc[i][1] = fma2(xl, wA0.y, acc[i][1]);
                acc[i][2] = fma2(xl, wB0.x, acc[i][2]);
                acc[i][3] = fma2(xl, wB0.y, acc[i][3]);
                acc[i][0] = fma2(xh, wA1.x, acc[i][0]);
                acc[i][1] = fma2(xh, wA1.y, acc[i][1]);
                acc[i][2] = fma2(xh, wB1.x, acc[i][2]);
                acc[i][3] = fma2(xh, wB1.y, acc[i][3]);
            }
        }

        // epilogue: gelu + dot with W2 for this h chunk
        int hbase = hc*128 + h0;
#pragma unroll
        for (int j = 0; j < 4; ++j) {
            float2 b1p = *(const float2*)(b1 + hbase + 2*j);
            float2 w2p = *(const float2*)(W2 + hbase + 2*j);
#pragma unroll
            for (int i = 0; i < 4; ++i) {
                float2 e = unpack2(acc[i][j]);
                sp[i] += gelu_exact(e.x + b1p.x) * w2p.x;
                sp[i] += gelu_exact(e.y + b1p.y) * w2p.y;
            }
        }
    }

    __syncthreads();
#pragma unroll
    for (int i = 0; i < 4; ++i) part[tx*PPITCH + t0 + i] = sp[i];
    __syncthreads();
    if (tid < 128) {
        float s = b2[0];
#pragma unroll
        for (int x = 0; x < 16; ++x) s += part[x*PPITCH + tid];
        g_scores[g0 + tid] = s;
    }
}

// ---------------- Kernel 5: normalize + top-k + compact ----------------
__device__ __forceinline__ unsigned long long mk_key(float f, int i) {
    unsigned u = __float_as_uint(f);
    u = (u & 0x80000000u) ? ~u : (u | 0x80000000u);  // order-preserving
    return (((unsigned long long)(~u)) << 32) | (unsigned)i; // desc score, asc idx
}

#define TOPK_SMEM (16384 + 32768 + 16384 + 512)
__global__ void __launch_bounds__(1024) topk_kernel(
    float* __restrict__ out_idx, float* __restrict__ out_scores)
{
    extern __shared__ unsigned char shraw[];
    float*              sc   = (float*)shraw;                         // [4096]
    unsigned long long* key  = (unsigned long long*)(shraw + 16384);  // [4096]
    int*                flag = (int*)(shraw + 16384 + 32768);         // [4096]
    float*              redf = (float*)(shraw + 16384 + 32768 + 16384); // 64 f
    int*                redi = (int*)(redf + 64);                     // 64 i

    int b = blockIdx.x, tid = threadIdx.x;
    int lane = tid & 31, wid = tid >> 5;
    int base4 = tid * 4;

    float4 v = *(const float4*)(g_scores + b*TT + base4);
    float s = v.x + v.y + v.z + v.w;
#pragma unroll
    for (int o = 16; o; o >>= 1) s += __shfl_down_sync(0xffffffffu, s, o);
    if (lane == 0) redf[wid] = s;
    __syncthreads();
    if (tid == 0) {
        float a = 0.f;
        for (int i = 0; i < 32; ++i) a += redf[i];
        redf[32] = a * (1.0f/TT);
    }
    __syncthreads();
    float mean = redf[32];
    float d0 = v.x-mean, d1 = v.y-mean, d2 = v.z-mean, d3 = v.w-mean;
    float q = d0*d0 + d1*d1 + d2*d2 + d3*d3;
    __syncthreads();
#pragma unroll
    for (int o = 16; o; o >>= 1) q += __shfl_down_sync(0xffffffffu, q, o);
    if (lane == 0) redf[wid] = q;
    __syncthreads();
    if (tid == 0) {
        float a = 0.f;
        for (int i = 0; i < 32; ++i) a += redf[i];
        redf[33] = 1.0f / (sqrtf(a * (1.0f/TT)) + 1e-6f);
    }
    __syncthreads();
    float inv = redf[33];
    float n0 = d0*inv, n1 = d1*inv, n2 = d2*inv, n3 = d3*inv;

    sc[base4+0] = n0; sc[base4+1] = n1; sc[base4+2] = n2; sc[base4+3] = n3;
    *(float4*)(out_scores + b*TT + base4) = make_float4(n0, n1, n2, n3);
    key[base4+0] = mk_key(n0, base4+0);
    key[base4+1] = mk_key(n1, base4+1);
    key[base4+2] = mk_key(n2, base4+2);
    key[base4+3] = mk_key(n3, base4+3);
    flag[base4+0] = 0; flag[base4+1] = 0; flag[base4+2] = 0; flag[base4+3] = 0;
    __syncthreads();

    // bitonic sort 4096 keys ascending
    for (int kk = 2; kk <= 4096; kk <<= 1) {
        for (int j = kk >> 1; j > 0; j >>= 1) {
#pragma unroll
            for (int p = 0; p < 4; ++p) {
                int i = tid + p*1024;
                int ixj = i ^ j;
                if (ixj > i) {
                    unsigned long long a = key[i], c2 = key[ixj];
                    bool asc = ((i & kk) == 0);
                    if ((a > c2) == asc) { key[i] = c2; key[ixj] = a; }
                }
            }
            __syncthreads();
        }
    }

    // mark top K (positions 0..2047)
    {
        int idx = (int)(unsigned)(key[tid] & 0xffffffffull);
        flag[idx] = 1;
        idx = (int)(unsigned)(key[tid + 1024] & 0xffffffffull);
        flag[idx] = 1;
    }
    __syncthreads();

    // prefix scan of flags, compact ascending
    int f0 = flag[base4], f1 = flag[base4+1], f2 = flag[base4+2], f3 = flag[base4+3];
    int tot = f0 + f1 + f2 + f3;
    int x = tot;
#pragma unroll
    for (int o = 1; o < 32; o <<= 1) {
        int y = __shfl_up_sync(0xffffffffu, x, o);
        if (lane >= o) x += y;
    }
    if (lane == 31) redi[wid] = x;
    __syncthreads();
    if (wid == 0) {
        int y = redi[lane];
        int z = y;
#pragma unroll
        for (int o = 1; o < 32; o <<= 1) {
            int w2 = __shfl_up_sync(0xffffffffu, z, o);
            if (lane >= o) z += w2;
        }
        redi[32 + lane] = z - y;   // exclusive
    }
    __syncthreads();
    int off = redi[32 + wid] + (x - tot);

    int flags[4] = {f0, f1, f2, f3};
#pragma unroll
    for (int qq = 0; qq < 4; ++qq) {
        if (flags[qq]) {
            int idx = base4 + qq;
            int pos = b*KK + off;
            g_selidx[pos] = idx;
            out_idx[pos]  = (float)idx;
            g_gate[pos]   = 1.0f + 0.1f * (1.0f / (1.0f + expf(-sc[idx])));
            ++off;
        }
    }
}

// ---------------- Kernel 6: gather + gate ----------------
__global__ void __launch_bounds__(256) gather_kernel(
    const float* __restrict__ tokens, float* __restrict__ out_sel)
{
    int bk  = blockIdx.x;          // b*K + kk
    int b   = bk >> 11;
    int idx = g_selidx[bk];
    float gate = g_gate[bk];
    const float4* src = (const float4*)(tokens + ((size_t)(b*TT + idx)) * (JJ*CC));
    float4* dst = (float4*)(out_sel + (size_t)bk * (JJ*CC));
#pragma unroll 2
    for (int i = threadIdx.x; i < (JJ*CC)/4; i += 256) {
        float4 v = src[i];
        v.x *= gate; v.y *= gate; v.z *= gate; v.w *= gate;
        dst[i] = v;
    }
}

// ---------------- launch ----------------
extern "C" void kernel_launch(void* const* d_in, const int* in_sizes, int n_in,
                              void* d_out, int out_size)
{
    const float* tokens = (const float*)d_in[0];
    const float* ln_w   = (const float*)d_in[1];
    const float* ln_b   = (const float*)d_in[2];
    const float* W1     = (const float*)d_in[3];
    const float* b1     = (const float*)d_in[4];
    const float* W2     = (const float*)d_in[5];
    const float* b2     = (const float*)d_in[6];

    float* out        = (float*)d_out;
    float* out_sel    = out;                       // [B,K,J,C]
    float* out_idx    = out + SEL_ELEMS;           // [B,K]
    float* out_scores = out_idx + IDX_ELEMS;       // [B,T]

    cudaFuncSetAttribute(mlp_kernel,
        cudaFuncAttributeMaxDynamicSharedMemorySize, MLP_SMEM);
    cudaFuncSetAttribute(topk_kernel,
        cudaFuncAttributeMaxDynamicSharedMemorySize, TOPK_SMEM);

    mean_ln_kernel<<<BT, 128>>>(tokens, ln_w, ln_b);
    gc_partial_kernel<<<dim3(BB, 32), 128>>>();
    gc_final_kernel<<<BB, 128>>>();
    mlp_kernel<<<BT/128, 512, MLP_SMEM>>>(W1, b1, W2, b2);
    topk_kernel<<<BB, 1024, TOPK_SMEM>>>(out_idx, out_scores);
    gather_kernel<<<BB*KK, 256>>>(tokens, out_sel);
}

// round 3
// speedup vs baseline: 1.2826x; 1.2826x over previous
#include <cuda_runtime.h>
#include <cstdint>
#include <math.h>

#define BB 16
#define TT 4096
#define JJ 17
#define CC 128
#define HH 512
#define KK 2048
#define BT (BB*TT)

#define SEL_ELEMS (BB*KK*JJ*CC)   // 71303168
#define IDX_ELEMS (BB*KK)         // 32768

// ---- scratch (static device arrays; no allocation allowed) ----
__device__ float g_stn[BT*CC];          // layernormed joint-mean  [B*T, C]
__device__ float g_gc_part[BB*32*CC];   // partial sums for global context
__device__ float g_gc[BB*CC];           // global context  [B, C]
__device__ float g_scores[BT];          // raw MLP scores  [B*T]
__device__ int   g_selidx[BB*KK];       // selected indices, ascending per batch
__device__ float g_gate[BB*KK];         // 1 + 0.1*sigmoid(score)

// ---------------- f32x2 helpers (Blackwell packed fp32) ----------------
__device__ __forceinline__ unsigned long long pack2(float x) {
    unsigned long long r;
    asm("mov.b64 %0, {%1, %1};" : "=l"(r) : "f"(x));
    return r;
}
__device__ __forceinline__ unsigned long long fma2(unsigned long long a,
                                                   unsigned long long b,
                                                   unsigned long long c) {
    unsigned long long d;
    asm("fma.rn.f32x2 %0, %1, %2, %3;" : "=l"(d) : "l"(a), "l"(b), "l"(c));
    return d;
}
__device__ __forceinline__ float2 unpack2(unsigned long long v) {
    float lo, hi;
    asm("mov.b64 {%0, %1}, %2;" : "=f"(lo), "=f"(hi) : "l"(v));
    return make_float2(lo, hi);
}

__device__ __forceinline__ float gelu_exact(float x) {
    return 0.5f * x * (1.0f + erff(x * 0.70710678118654752440f));
}

// ---------------- Kernel 1: joint mean + LayerNorm ----------------
__global__ void __launch_bounds__(128) mean_ln_kernel(
    const float* __restrict__ tokens,
    const float* __restrict__ ln_w,
    const float* __restrict__ ln_b)
{
    int bt = blockIdx.x;
    int c  = threadIdx.x;
    const float* src = tokens + (size_t)bt * (JJ*CC) + c;
    float s = 0.f;
#pragma unroll
    for (int j = 0; j < JJ; ++j) s += src[(size_t)j*CC];
    float st = s * (1.0f/17.0f);

    __shared__ float red[64];
    float v = st, v2 = st*st;
#pragma unroll
    for (int o = 16; o; o >>= 1) {
        v  += __shfl_down_sync(0xffffffffu, v,  o);
        v2 += __shfl_down_sync(0xffffffffu, v2, o);
    }
    int wid = c >> 5, lane = c & 31;
    if (lane == 0) { red[wid] = v; red[32+wid] = v2; }
    __syncthreads();
    if (c == 0) {
        float a = red[0]+red[1]+red[2]+red[3];
        float b = red[32]+red[33]+red[34]+red[35];
        red[40] = a * (1.0f/128.0f);
        red[41] = b * (1.0f/128.0f);
    }
    __syncthreads();
    float mu  = red[40];
    float var = red[41] - mu*mu;
    float inv = rsqrtf(var + 1e-5f);
    g_stn[(size_t)bt*CC + c] = (st - mu) * inv * ln_w[c] + ln_b[c];
}

// ---------------- Kernel 2/3: global context reduce ----------------
__global__ void __launch_bounds__(128) gc_partial_kernel()
{
    int b = blockIdx.x, chunk = blockIdx.y, c = threadIdx.x;
    const float* p = g_stn + ((size_t)(b*TT + chunk*128))*CC + c;
    float s = 0.f;
#pragma unroll 8
    for (int t = 0; t < 128; ++t) s += p[(size_t)t*CC];
    g_gc_part[(b*32 + chunk)*CC + c] = s;
}

__global__ void __launch_bounds__(128) gc_final_kernel()
{
    int b = blockIdx.x, c = threadIdx.x;
    float s = 0.f;
#pragma unroll
    for (int k = 0; k < 32; ++k) s += g_gc_part[(b*32 + k)*CC + c];
    g_gc[b*CC + c] = s * (1.0f/4096.0f);
}

// ---------------- Kernel 4: MLP scoring (fp32 GEMM via f32x2) ----------------
// 256 threads; block tile 128 tokens x 256 h per chunk (2 chunks of H=512).
// Thread tile: 8 tokens x 16 h.
//   x: natural [t][k] layout, pitch 132 (broadcast LDS.32, conflict-free)
//   w: [k][256], thread's 16 h = tx*4 + {0..3} + 64*q (consecutive-16B LDS.128)
#define XPITCH 132
#define PPITCH 132
#define MLP_SMEM ((128*XPITCH + 128*256 + 16*PPITCH) * 4)
__global__ void __launch_bounds__(256, 1) mlp_kernel(
    const float* __restrict__ W1,
    const float* __restrict__ b1,
    const float* __restrict__ W2,
    const float* __restrict__ b2)
{
    extern __shared__ float sh[];
    float* xs   = sh;                        // [128 t][pitch 132]
    float* ws   = sh + 128*XPITCH;           // [128 k][256 h]
    float* part = sh + 128*XPITCH + 128*256; // [16][pitch 132]

    int tid = threadIdx.x;
    int g0  = blockIdx.x * 128;
    int b   = g0 >> 12;

    // stage x (natural layout, +gc); fully coalesced, conflict-free stores
#pragma unroll
    for (int r = 0; r < 16; ++r) {
        int i  = r*256 + tid;
        int t  = i >> 5;
        int kq = (i & 31) * 4;
        float4 x4 = *(const float4*)(g_stn + (size_t)(g0 + t)*CC + kq);
        float4 g4 = *(const float4*)(g_gc + b*CC + kq);
        x4.x += g4.x; x4.y += g4.y; x4.z += g4.z; x4.w += g4.w;
        *(float4*)(xs + t*XPITCH + kq) = x4;
    }

    int tx = tid & 15;            // h-quad group: h = tx*4+{0..3} + 64*q
    int ty = tid >> 4;            // token group:  t = ty*4+{0..3} and +64
    int t0 = ty * 4;

    float sp[8] = {0.f,0.f,0.f,0.f,0.f,0.f,0.f,0.f};

    for (int hc = 0; hc < 2; ++hc) {
        __syncthreads();   // xs ready / previous ws consumed
#pragma unroll
        for (int r = 0; r < 32; ++r) {
            int i = r*256 + tid;
            int k = i >> 6;
            int q = (i & 63) * 4;
            *(float4*)(ws + k*256 + q) =
                *(const float4*)(W1 + (size_t)k*HH + hc*256 + q);
        }
        __syncthreads();

        unsigned long long acc[8][8];
#pragma unroll
        for (int i = 0; i < 8; ++i)
#pragma unroll
            for (int j = 0; j < 8; ++j) acc[i][j] = 0ull;

        for (int k = 0; k < 128; ++k) {
            // x: 8 tokens, broadcast scalar loads
            const float* xc = xs + k;
            unsigned long long xp[8];
#pragma unroll
            for (int i = 0; i < 4; ++i) {
                xp[i]   = pack2(xc[(t0+i)*XPITCH]);
                xp[4+i] = pack2(xc[(64+t0+i)*XPITCH]);
            }
            // w: 16 h as 4 conflict-free LDS.128 (h-pairs packed free)
            const float* wr = ws + k*256 + tx*4;
            ulonglong2 w0 = *(const ulonglong2*)(wr);
            ulonglong2 w1 = *(const ulonglong2*)(wr + 64);
            ulonglong2 w2 = *(const ulonglong2*)(wr + 128);
            ulonglong2 w3 = *(const ulonglong2*)(wr + 192);
#pragma unroll
            for (int i = 0; i < 8; ++i) {
                acc[i][0] = fma2(xp[i], w0.x, acc[i][0]);
                acc[i][1] = fma2(xp[i], w0.y, acc[i][1]);
                acc[i][2] = fma2(xp[i], w1.x, acc[i][2]);
                acc[i][3] = fma2(xp[i], w1.y, acc[i][3]);
                acc[i][4] = fma2(xp[i], w2.x, acc[i][4]);
                acc[i][5] = fma2(xp[i], w2.y, acc[i][5]);
                acc[i][6] = fma2(xp[i], w3.x, acc[i][6]);
                acc[i][7] = fma2(xp[i], w3.y, acc[i][7]);
            }
        }

        // epilogue: gelu + dot with W2 for this chunk
#pragma unroll
        for (int q = 0; q < 4; ++q) {
            int hb = hc*256 + q*64 + tx*4;
            float4 b1q = *(const float4*)(b1 + hb);
            float4 w2q = *(const float4*)(W2 + hb);
#pragma unroll
            for (int i = 0; i < 8; ++i) {
                float2 e0 = unpack2(acc[i][q*2]);
                float2 e1 = unpack2(acc[i][q*2+1]);
                sp[i] += gelu_exact(e0.x + b1q.x) * w2q.x;
                sp[i] += gelu_exact(e0.y + b1q.y) * w2q.y;
                sp[i] += gelu_exact(e1.x + b1q.z) * w2q.z;
                sp[i] += gelu_exact(e1.y + b1q.w) * w2q.w;
            }
        }
    }

    __syncthreads();
#pragma unroll
    for (int i = 0; i < 4; ++i) {
        part[tx*PPITCH + t0 + i]      = sp[i];
        part[tx*PPITCH + 64 + t0 + i] = sp[4+i];
    }
    __syncthreads();
    if (tid < 128) {
        float s = b2[0];
#pragma unroll
        for (int x = 0; x < 16; ++x) s += part[x*PPITCH + tid];
        g_scores[g0 + tid] = s;
    }
}

// ---------------- Kernel 5: normalize + top-k + compact ----------------
__device__ __forceinline__ unsigned long long mk_key(float f, int i) {
    unsigned u = __float_as_uint(f);
    u = (u & 0x80000000u) ? ~u : (u | 0x80000000u);  // order-preserving
    return (((unsigned long long)(~u)) << 32) | (unsigned)i; // desc score, asc idx
}

#define TOPK_SMEM (16384 + 32768 + 16384 + 512)
__global__ void __launch_bounds__(1024) topk_kernel(
    float* __restrict__ out_idx, float* __restrict__ out_scores)
{
    extern __shared__ unsigned char shraw[];
    float*              sc   = (float*)shraw;                         // [4096]
    unsigned long long* key  = (unsigned long long*)(shraw + 16384);  // [4096]
    int*                flag = (int*)(shraw + 16384 + 32768);         // [4096]
    float*              redf = (float*)(shraw + 16384 + 32768 + 16384); // 64 f
    int*                redi = (int*)(redf + 64);                     // 64 i

    int b = blockIdx.x, tid = threadIdx.x;
    int lane = tid & 31, wid = tid >> 5;
    int base4 = tid * 4;

    float4 v = *(const float4*)(g_scores + b*TT + base4);
    float s = v.x + v.y + v.z + v.w;
#pragma unroll
    for (int o = 16; o; o >>= 1) s += __shfl_down_sync(0xffffffffu, s, o);
    if (lane == 0) redf[wid] = s;
    __syncthreads();
    if (tid == 0) {
        float a = 0.f;
        for (int i = 0; i < 32; ++i) a += redf[i];
        redf[32] = a * (1.0f/TT);
    }
    __syncthreads();
    float mean = redf[32];
    float d0 = v.x-mean, d1 = v.y-mean, d2 = v.z-mean, d3 = v.w-mean;
    float q = d0*d0 + d1*d1 + d2*d2 + d3*d3;
    __syncthreads();
#pragma unroll
    for (int o = 16; o; o >>= 1) q += __shfl_down_sync(0xffffffffu, q, o);
    if (lane == 0) redf[wid] = q;
    __syncthreads();
    if (tid == 0) {
        float a = 0.f;
        for (int i = 0; i < 32; ++i) a += redf[i];
        redf[33] = 1.0f / (sqrtf(a * (1.0f/TT)) + 1e-6f);
    }
    __syncthreads();
    float inv = redf[33];
    float n0 = d0*inv, n1 = d1*inv, n2 = d2*inv, n3 = d3*inv;

    sc[base4+0] = n0; sc[base4+1] = n1; sc[base4+2] = n2; sc[base4+3] = n3;
    *(float4*)(out_scores + b*TT + base4) = make_float4(n0, n1, n2, n3);
    key[base4+0] = mk_key(n0, base4+0);
    key[base4+1] = mk_key(n1, base4+1);
    key[base4+2] = mk_key(n2, base4+2);
    key[base4+3] = mk_key(n3, base4+3);
    flag[base4+0] = 0; flag[base4+1] = 0; flag[base4+2] = 0; flag[base4+3] = 0;
    __syncthreads();

    // bitonic sort 4096 keys ascending
    for (int kk = 2; kk <= 4096; kk <<= 1) {
        for (int j = kk >> 1; j > 0; j >>= 1) {
#pragma unroll
            for (int p = 0; p < 4; ++p) {
                int i = tid + p*1024;
                int ixj = i ^ j;
                if (ixj > i) {
                    unsigned long long a = key[i], c2 = key[ixj];
                    bool asc = ((i & kk) == 0);
                    if ((a > c2) == asc) { key[i] = c2; key[ixj] = a; }
                }
            }
            __syncthreads();
        }
    }

    // mark top K (positions 0..2047)
    {
        int idx = (int)(unsigned)(key[tid] & 0xffffffffull);
        flag[idx] = 1;
        idx = (int)(unsigned)(key[tid + 1024] & 0xffffffffull);
        flag[idx] = 1;
    }
    __syncthreads();

    // prefix scan of flags, compact ascending
    int f0 = flag[base4], f1 = flag[base4+1], f2 = flag[base4+2], f3 = flag[base4+3];
    int tot = f0 + f1 + f2 + f3;
    int x = tot;
#pragma unroll
    for (int o = 1; o < 32; o <<= 1) {
        int y = __shfl_up_sync(0xffffffffu, x, o);
        if (lane >= o) x += y;
    }
    if (lane == 31) redi[wid] = x;
    __syncthreads();
    if (wid == 0) {
        int y = redi[lane];
        int z = y;
#pragma unroll
        for (int o = 1; o < 32; o <<= 1) {
            int w2 = __shfl_up_sync(0xffffffffu, z, o);
            if (lane >= o) z += w2;
        }
        redi[32 + lane] = z - y;   // exclusive
    }
    __syncthreads();
    int off = redi[32 + wid] + (x - tot);

    int flags[4] = {f0, f1, f2, f3};
#pragma unroll
    for (int qq = 0; qq < 4; ++qq) {
        if (flags[qq]) {
            int idx = base4 + qq;
            int pos = b*KK + off;
            g_selidx[pos] = idx;
            out_idx[pos]  = (float)idx;
            g_gate[pos]   = 1.0f + 0.1f * (1.0f / (1.0f + expf(-sc[idx])));
            ++off;
        }
    }
}

// ---------------- Kernel 6: gather + gate ----------------
__global__ void __launch_bounds__(256) gather_kernel(
    const float* __restrict__ tokens, float* __restrict__ out_sel)
{
    int bk  = blockIdx.x;          // b*K + kk
    int b   = bk >> 11;
    int idx = g_selidx[bk];
    float gate = g_gate[bk];
    const float4* src = (const float4*)(tokens + ((size_t)(b*TT + idx)) * (JJ*CC));
    float4* dst = (float4*)(out_sel + (size_t)bk * (JJ*CC));
#pragma unroll 2
    for (int i = threadIdx.x; i < (JJ*CC)/4; i += 256) {
        float4 v = src[i];
        v.x *= gate; v.y *= gate; v.z *= gate; v.w *= gate;
        dst[i] = v;
    }
}

// ---------------- launch ----------------
extern "C" void kernel_launch(void* const* d_in, const int* in_sizes, int n_in,
                              void* d_out, int out_size)
{
    const float* tokens = (const float*)d_in[0];
    const float* ln_w   = (const float*)d_in[1];
    const float* ln_b   = (const float*)d_in[2];
    const float* W1     = (const float*)d_in[3];
    const float* b1     = (const float*)d_in[4];
    const float* W2     = (const float*)d_in[5];
    const float* b2     = (const float*)d_in[6];

    float* out        = (float*)d_out;
    float* out_sel    = out;                       // [B,K,J,C]
    float* out_idx    = out + SEL_ELEMS;           // [B,K]
    float* out_scores = out_idx + IDX_ELEMS;       // [B,T]

    cudaFuncSetAttribute(mlp_kernel,
        cudaFuncAttributeMaxDynamicSharedMemorySize, MLP_SMEM);
    cudaFuncSetAttribute(topk_kernel,
        cudaFuncAttributeMaxDynamicSharedMemorySize, TOPK_SMEM);

    mean_ln_kernel<<<BT, 128>>>(tokens, ln_w, ln_b);
    gc_partial_kernel<<<dim3(BB, 32), 128>>>();
    gc_final_kernel<<<BB, 128>>>();
    mlp_kernel<<<BT/128, 256, MLP_SMEM>>>(W1, b1, W2, b2);
    topk_kernel<<<BB, 1024, TOPK_SMEM>>>(out_idx, out_scores);
    gather_kernel<<<BB*KK, 256>>>(tokens, out_sel);
}